// round 9
// baseline (speedup 1.0000x reference)
#include <cuda_runtime.h>

// Problem constants
#define BATCH 32
#define IMG_H 480
#define IMG_W 640
#define OUT_H 470
#define OUT_W 630
#define WS    11

// Tiling: 32 wide x 64 tall
#define TILE_W 32
#define TILE_H 64
#define IN_W   (TILE_W + WS - 1)   // 42
#define IN_H   (TILE_H + WS - 1)   // 74
#define MID_W  TILE_W              // 32

#define GX 20   // ceil(630/32)
#define GY 8    // ceil(470/64)
#define NBLOCKS (GX * GY * BATCH)  // 5120
#define NTHREADS 512

// Normalized 1D Gaussian, sigma=1.5, ws=11 (symmetric)
static __device__ __forceinline__ float gw(int t) {
    constexpr float w[11] = {
        0.00102839f, 0.00759866f, 0.03600077f, 0.10936124f, 0.21300553f,
        0.26601172f,
        0.21300553f, 0.10936124f, 0.03600077f, 0.00759866f, 0.00102839f
    };
    return w[t];
}

__device__ float        g_partials[NBLOCKS];
__device__ unsigned int g_count = 0;

__global__ __launch_bounds__(NTHREADS, 3)
void ssim_tile_kernel(const float* __restrict__ img1,
                      const float* __restrict__ img2,
                      float* __restrict__ out)
{
    extern __shared__ float smem[];
    float4* s_mid = (float4*)smem;               // IN_H * MID_W  (Ms,Md,Es,Ed)

    __shared__ float    s_red[NTHREADS / 32];
    __shared__ unsigned s_flag;

    const int tid = threadIdx.x;
    const int bz  = blockIdx.z;
    const int r0  = blockIdx.y * TILE_H;
    const int c0  = blockIdx.x * TILE_W;

    const float* im1 = img1 + (size_t)bz * IMG_H * IMG_W;
    const float* im2 = img2 + (size_t)bz * IMG_H * IMG_W;

    // ---- Stage A: fused global load + horizontal conv -> mid in smem ----
    // 592 strips (74 rows x 8 quads of 4 outputs). Halo re-reads served by L1D.
    const bool interior = (c0 + 44 <= IMG_W) && (r0 + IN_H <= IMG_H);

    for (int st = tid; st < IN_H * (TILE_W / 4); st += NTHREADS) {
        int row = st >> 3;            // st / 8
        int cq  = (st & 7) << 2;      // (st % 8) * 4

        float sv[16], dv[16];
        if (interior) {
            // 16B-aligned (IMG_W, c0, cq all multiples of 4): 4+4 LDG.128
            const float4* p1 = (const float4*)(im1 + (size_t)(r0 + row) * IMG_W + c0 + cq);
            const float4* p2 = (const float4*)(im2 + (size_t)(r0 + row) * IMG_W + c0 + cq);
            #pragma unroll
            for (int i = 0; i < 4; i++) {
                float4 a = __ldg(p1 + i);
                float4 b = __ldg(p2 + i);
                sv[4*i+0] = a.x + b.x; dv[4*i+0] = a.x - b.x;
                sv[4*i+1] = a.y + b.y; dv[4*i+1] = a.y - b.y;
                sv[4*i+2] = a.z + b.z; dv[4*i+2] = a.z - b.z;
                sv[4*i+3] = a.w + b.w; dv[4*i+3] = a.w - b.w;
            }
        } else {
            int gr = r0 + row;
            #pragma unroll
            for (int i = 0; i < 16; i++) {
                int gc = c0 + cq + i;
                float a = 0.f, b = 0.f;
                if (gr < IMG_H && gc < IMG_W) {
                    int idx = gr * IMG_W + gc;
                    a = __ldg(im1 + idx);
                    b = __ldg(im2 + idx);
                }
                sv[i] = a + b;
                dv[i] = a - b;
            }
        }

        float aMs[4] = {0.f, 0.f, 0.f, 0.f};
        float aMd[4] = {0.f, 0.f, 0.f, 0.f};
        float aEs[4] = {0.f, 0.f, 0.f, 0.f};
        float aEd[4] = {0.f, 0.f, 0.f, 0.f};

        #pragma unroll
        for (int k = 0; k < WS + 3; k++) {   // 14 taps serve 4 outputs
            float skv = sv[k];
            float dkv = dv[k];
            float ss  = skv * skv;
            float dd  = dkv * dkv;
            #pragma unroll
            for (int o = 0; o < 4; o++) {
                int t = k - o;
                if (t >= 0 && t < WS) {      // compile-time resolved
                    float w = gw(t);         // literal -> FFMA-imm (rt=1)
                    aMs[o] = fmaf(w, skv, aMs[o]);
                    aMd[o] = fmaf(w, dkv, aMd[o]);
                    aEs[o] = fmaf(w, ss,  aEs[o]);
                    aEd[o] = fmaf(w, dd,  aEd[o]);
                }
            }
        }
        float4* m = s_mid + row * MID_W + cq;
        #pragma unroll
        for (int o = 0; o < 4; o++)
            m[o] = make_float4(aMs[o], aMd[o], aEs[o], aEd[o]);  // STS.128
    }
    __syncthreads();

    // ---- Stage B: vertical conv + SSIM + local sum; 512 strips == NTHREADS ----
    const float C1 = 1.0f;   // (0.01*100)^2
    const float C2 = 9.0f;   // (0.03*100)^2
    float lsum = 0.f;

    {
        int c  = tid & (TILE_W - 1);
        int rq = (tid >> 5) << 2;

        float Ms[4] = {0.f, 0.f, 0.f, 0.f};
        float Md[4] = {0.f, 0.f, 0.f, 0.f};
        float Es[4] = {0.f, 0.f, 0.f, 0.f};
        float Ed[4] = {0.f, 0.f, 0.f, 0.f};

        #pragma unroll
        for (int k = 0; k < WS + 3; k++) {
            float4 v = s_mid[(rq + k) * MID_W + c];   // one LDS.128 per tap
            #pragma unroll
            for (int o = 0; o < 4; o++) {
                int t = k - o;
                if (t >= 0 && t < WS) {
                    float w = gw(t);
                    Ms[o] = fmaf(w, v.x, Ms[o]);
                    Md[o] = fmaf(w, v.y, Md[o]);
                    Es[o] = fmaf(w, v.z, Es[o]);
                    Ed[o] = fmaf(w, v.w, Ed[o]);
                }
            }
        }

        int gc = c0 + c;
        if (gc < OUT_W) {
            #pragma unroll
            for (int o = 0; o < 4; o++) {
                int gr = r0 + rq + o;
                if (gr < OUT_H) {
                    float ms = Ms[o], md = Md[o];
                    float ms2 = ms * ms;
                    float md2 = md * md;
                    float Ps = Es[o] - ms2;     // s1+s2+2*s12
                    float Qd = Ed[o] - md2;     // s1+s2-2*s12
                    float v1 = 0.5f * (Ps - Qd) + C2;            // 2*s12 + C2
                    float v2 = 0.5f * (Ps + Qd) + C2;            // s1+s2 + C2
                    float num = (0.5f * (ms2 - md2) + C1) * v1;  // (2*mu12+C1)*v1
                    float den = (0.5f * (ms2 + md2) + C1) * v2;  // (mu1^2+mu2^2+C1)*v2
                    lsum += __fdividef(num, den);
                }
            }
        }
    }

    // ---- Stage C: block partial + fused last-block finalize ----
    #pragma unroll
    for (int off = 16; off > 0; off >>= 1)
        lsum += __shfl_down_sync(0xffffffffu, lsum, off);

    int warp = tid >> 5;
    int lane = tid & 31;
    if (lane == 0) s_red[warp] = lsum;
    __syncthreads();
    if (tid == 0) {
        float t = 0.f;
        #pragma unroll
        for (int i = 0; i < NTHREADS / 32; i++) t += s_red[i];
        int bidx = (blockIdx.z * GY + blockIdx.y) * GX + blockIdx.x;
        g_partials[bidx] = t;
        __threadfence();
        unsigned v = atomicAdd(&g_count, 1u);
        s_flag = (v == (unsigned)(NBLOCKS - 1));
    }
    __syncthreads();

    if (s_flag) {
        // deterministic: fixed summation order independent of which block runs this
        float acc = 0.f;
        for (int i = tid; i < NBLOCKS; i += NTHREADS)
            acc += __ldcg(&g_partials[i]);
        #pragma unroll
        for (int off = 16; off > 0; off >>= 1)
            acc += __shfl_down_sync(0xffffffffu, acc, off);
        if (lane == 0) s_red[warp] = acc;
        __syncthreads();
        if (tid == 0) {
            float tt = 0.f;
            #pragma unroll
            for (int i = 0; i < NTHREADS / 32; i++) tt += s_red[i];
            float mean = tt * (1.0f / ((float)BATCH * OUT_H * OUT_W));
            out[0] = (1.0f - mean) * 0.5f;
            g_count = 0;   // reset for next graph replay
        }
    }
}

extern "C" void kernel_launch(void* const* d_in, const int* in_sizes, int n_in,
                              void* d_out, int out_size)
{
    const float* img1 = (const float*)d_in[0];
    const float* img2 = (const float*)d_in[1];
    float* out = (float*)d_out;

    size_t smem_bytes = (size_t)(IN_H * MID_W) * sizeof(float4);
    cudaFuncSetAttribute(ssim_tile_kernel,
                         cudaFuncAttributeMaxDynamicSharedMemorySize,
                         (int)smem_bytes);

    dim3 grid(GX, GY, BATCH);
    ssim_tile_kernel<<<grid, NTHREADS, smem_bytes>>>(img1, img2, out);
}